// round 6
// baseline (speedup 1.0000x reference)
#include <cuda_runtime.h>
#include <cuda_fp16.h>
#include <cstdint>
#include <math.h>

#define NB 4
#define NN 512
#define NC 128

// logit scratch (4 MB)
__device__ float g_logits[NB * NN * NN];

// pre-split fp16 weights (hi/lo residual), permuted chunk layout.
// per layer: NCH chunks of [N*16 hi half2][N*16 lo half2]
// sizes(words): w1 192x128 -> 24576 | w2 192x192 -> 36864 | w3 96x192 -> 18432 | w4 96x96 -> 9216
#define WOFF1 0
#define WOFF2 24576
#define WOFF3 61440
#define WOFF4 79872
__device__ __align__(16) uint32_t g_wh[89088];

#define PL 14336   // activation plane stride (words) = 128*112

__device__ __forceinline__ float lrelu(float v) { return v > 0.f ? v : 0.01f * v; }
__device__ __forceinline__ int perm16(int w) { return (w & 3) * 4 + (w >> 2); }

// D(16x8,f32) += A(16x16,f16,row) * B(16x8,f16,col)
__device__ __forceinline__ void mma16(float* d, uint32_t a0, uint32_t a1, uint32_t a2, uint32_t a3,
                                      uint32_t b0, uint32_t b1) {
    asm volatile("mma.sync.aligned.m16n8k16.row.col.f32.f16.f16.f32 "
                 "{%0,%1,%2,%3},{%4,%5,%6,%7},{%8,%9},{%0,%1,%2,%3};"
                 : "+f"(d[0]), "+f"(d[1]), "+f"(d[2]), "+f"(d[3])
                 : "r"(a0), "r"(a1), "r"(a2), "r"(a3), "r"(b0), "r"(b1));
}

#define CP_ASYNC16(dst_u32, src_ptr) \
    asm volatile("cp.async.cg.shared.global [%0], [%1], 16;" :: "r"(dst_u32), "l"(src_ptr) : "memory")
#define CP_COMMIT() asm volatile("cp.async.commit_group;" ::: "memory")
#define CP_WAIT0()  asm volatile("cp.async.wait_group 0;" ::: "memory")

__device__ __forceinline__ uint32_t smem_u32(const void* p) {
    uint32_t a;
    asm("{ .reg .u64 t; cvta.to.shared.u64 t, %1; cvt.u32.u64 %0, t; }" : "=r"(a) : "l"(p));
    return a;
}

// Split fp32 weights [N][K] into fp16 hi + fp16 residual, permuted chunk layout.
__global__ void convert_weights(const float* __restrict__ W, int N, int K, int off)
{
    int idx = blockIdx.x * 256 + threadIdx.x;
    int kh = K >> 1;
    if (idx >= N * kh) return;
    int n = idx / kh, kp = idx - n * kh;
    int c = kp >> 4, w = kp & 15;
    float w0 = W[n * K + 2 * kp], w1 = W[n * K + 2 * kp + 1];
    __half2 h = __floats2half2_rn(w0, w1);
    float2 f = __half22float2(h);
    __half2 l = __floats2half2_rn(w0 - f.x, w1 - f.y);
    int base = off + c * N * 32;
    g_wh[base + n * 16 + perm16(w)]          = *(uint32_t*)&h;
    g_wh[base + N * 16 + n * 16 + perm16(w)] = *(uint32_t*)&l;
}

// Stage one chunk (2*N*16 words contiguous) via 16B cp.async.
__device__ __forceinline__ void stage_chunk(const uint32_t* __restrict__ gw, uint32_t dst_bytes,
                                            int units16, int tid) {
    for (int u = tid; u < units16; u += 512)
        CP_ASYNC16(dst_bytes + (uint32_t)(u * 16), (const char*)gw + u * 16);
    CP_COMMIT();
}

// One MLP layer, in-place on hi/lo activation planes (half2 words, row strides SA->SO).
// 3-term split MMA: D += AhWh + AlWh + AhWl. Requires chunk0 staged in sWa.
template <int N, int K, int SA, int SO>
__device__ void layer(uint32_t* __restrict__ bufH, const uint32_t* __restrict__ gw,
                      const float* __restrict__ bias,
                      const uint32_t* __restrict__ sWa, const uint32_t* __restrict__ sWb,
                      uint32_t swa_bytes, uint32_t swb_bytes, int tid)
{
    constexpr int NT  = N / 32;
    constexpr int NCH = K / 32;
    constexpr int U16 = N * 8;          // 16B units per chunk (hi+lo)

    uint32_t* bufL = bufH + PL;
    const int wid = tid >> 5, lane = tid & 31;
    const int g = lane >> 2, t = lane & 3;
    const int mb  = (wid & 3) * 32;
    const int nwb = (wid >> 2) * (N / 4);

    float d[2][NT][4];
#pragma unroll
    for (int mt = 0; mt < 2; ++mt)
#pragma unroll
        for (int nt = 0; nt < NT; ++nt)
#pragma unroll
            for (int q = 0; q < 4; ++q) d[mt][nt][q] = 0.f;

    for (int c = 0; c < NCH; ++c) {
        if (c + 1 < NCH)
            stage_chunk(gw + (c + 1) * N * 32,
                        ((c + 1) & 1) ? swb_bytes : swa_bytes, U16, tid);

        const uint32_t* sWc = (c & 1) ? sWb : sWa;
#pragma unroll
        for (int h = 0; h < 2; ++h) {
            const int ko = c * 16 + t * 4 + 2 * h;
            uint2 AH[2][2], AL[2][2];
#pragma unroll
            for (int mt = 0; mt < 2; ++mt) {
                int r0 = mb + mt * 16 + g;
                AH[mt][0] = *(const uint2*)(bufH + r0 * SA + ko);
                AH[mt][1] = *(const uint2*)(bufH + (r0 + 8) * SA + ko);
                AL[mt][0] = *(const uint2*)(bufL + r0 * SA + ko);
                AL[mt][1] = *(const uint2*)(bufL + (r0 + 8) * SA + ko);
            }
#pragma unroll
            for (int nt = 0; nt < NT; ++nt) {
                int n = nwb + nt * 8 + g;
                uint2 BH = *(const uint2*)(sWc + n * 16 + t * 4 + 2 * h);
                uint2 BL = *(const uint2*)(sWc + N * 16 + n * 16 + t * 4 + 2 * h);
#pragma unroll
                for (int mt = 0; mt < 2; ++mt) {
                    mma16(d[mt][nt], AH[mt][0].x, AH[mt][1].x, AH[mt][0].y, AH[mt][1].y, BH.x, BH.y);
                    mma16(d[mt][nt], AL[mt][0].x, AL[mt][1].x, AL[mt][0].y, AL[mt][1].y, BH.x, BH.y);
                    mma16(d[mt][nt], AH[mt][0].x, AH[mt][1].x, AH[mt][0].y, AH[mt][1].y, BL.x, BL.y);
                }
            }
        }
        if (c + 1 < NCH) CP_WAIT0();
        __syncthreads();
    }

    // epilogue: bias + lrelu -> split fp16 hi/lo, in place (input dead after sync), permuted
#pragma unroll
    for (int mt = 0; mt < 2; ++mt) {
        int r0 = mb + mt * 16 + g;
#pragma unroll
        for (int nt = 0; nt < NT; ++nt) {
            int cb = nwb + nt * 8 + 2 * t;
            int wcol = cb >> 1;
            int pos = (wcol >> 4) * 16 + perm16(wcol & 15);
            float bb0 = bias[cb], bb1 = bias[cb + 1];
            float v0 = lrelu(d[mt][nt][0] + bb0), v1 = lrelu(d[mt][nt][1] + bb1);
            float v2 = lrelu(d[mt][nt][2] + bb0), v3 = lrelu(d[mt][nt][3] + bb1);
            __half2 h0 = __floats2half2_rn(v0, v1);
            float2 f0 = __half22float2(h0);
            __half2 l0 = __floats2half2_rn(v0 - f0.x, v1 - f0.y);
            __half2 h1 = __floats2half2_rn(v2, v3);
            float2 f1 = __half22float2(h1);
            __half2 l1 = __floats2half2_rn(v2 - f1.x, v3 - f1.y);
            bufH[r0 * SO + pos]       = *(uint32_t*)&h0;
            bufL[r0 * SO + pos]       = *(uint32_t*)&l0;
            bufH[(r0 + 8) * SO + pos] = *(uint32_t*)&h1;
            bufL[(r0 + 8) * SO + pos] = *(uint32_t*)&l1;
        }
    }
    // caller stages next chunk0 and syncs
}

extern __shared__ uint32_t dynsm[];

__global__ void __launch_bounds__(512, 1)
mlp_kernel(const float* __restrict__ x,
           const float* __restrict__ b1, const float* __restrict__ b2,
           const float* __restrict__ b3, const float* __restrict__ b4,
           const float* __restrict__ w5, const float* __restrict__ b5)
{
    __shared__ float sXi[NC];
    __shared__ float sBias[576];
    __shared__ float sW5[96];
    __shared__ float sB5;

    const int tid = threadIdx.x;

    // block -> (b, i, jt) over symmetric 128-tiles: jt >= block(i)
    int blk = blockIdx.x;
    int b = blk / 1280;
    int t = blk - b * 1280;
    int ib, local, cnt;
    if (t < 512)       { ib = 0; local = t;        cnt = 4; }
    else if (t < 896)  { ib = 1; local = t - 512;  cnt = 3; }
    else if (t < 1152) { ib = 2; local = t - 896;  cnt = 2; }
    else               { ib = 3; local = t - 1152; cnt = 1; }
    const int i  = ib * 128 + local / cnt;
    const int jt = ib + local % cnt;
    const int j0 = jt * 128;

    const float* xb = x + (size_t)b * NN * NC;

    uint32_t* bufH = dynsm;                 // hi plane [128 x 112]
    uint32_t* bufL = bufH + PL;             // lo plane
    uint32_t* sWa  = bufH + 2 * PL;         // 192*32 words
    uint32_t* sWb  = sWa + 192 * 32;
    const uint32_t swa_bytes = smem_u32(sWa);
    const uint32_t swb_bytes = smem_u32(sWb);

    if (tid < 128) sXi[tid] = xb[(size_t)i * NC + tid];
    if (tid < 192) { sBias[tid] = b1[tid]; sBias[192 + tid] = b2[tid]; }
    if (tid < 96)  { sBias[384 + tid] = b3[tid]; sBias[480 + tid] = b4[tid]; sW5[tid] = w5[tid]; }
    if (tid == 0)  sB5 = b5[0];
    __syncthreads();   // sXi ready

    // stage w1 chunk0 while doing the prologue
    stage_chunk(g_wh + WOFF1, swa_bytes, 192 * 8, tid);

    // prologue: split fp16 |x_i - x_j| pairs, row stride 80, permuted
    for (int idx = tid; idx < 128 * 64; idx += 512) {
        int r = idx >> 6, kp = idx & 63;
        float2 xj = *(const float2*)(xb + (size_t)(j0 + r) * NC + 2 * kp);
        float v0 = fabsf(sXi[2 * kp] - xj.x), v1 = fabsf(sXi[2 * kp + 1] - xj.y);
        __half2 h = __floats2half2_rn(v0, v1);
        float2 f = __half22float2(h);
        __half2 l = __floats2half2_rn(v0 - f.x, v1 - f.y);
        int pos = r * 80 + (kp >> 4) * 16 + perm16(kp & 15);
        bufH[pos] = *(uint32_t*)&h;
        bufL[pos] = *(uint32_t*)&l;
    }
    CP_WAIT0();
    __syncthreads();

    layer<192, 128, 80, 112>(bufH, g_wh + WOFF1, sBias + 0,   sWa, sWb, swa_bytes, swb_bytes, tid);
    stage_chunk(g_wh + WOFF2, swa_bytes, 192 * 8, tid); CP_WAIT0(); __syncthreads();
    layer<192, 192, 112, 112>(bufH, g_wh + WOFF2, sBias + 192, sWa, sWb, swa_bytes, swb_bytes, tid);
    stage_chunk(g_wh + WOFF3, swa_bytes, 96 * 8, tid);  CP_WAIT0(); __syncthreads();
    layer<96, 192, 112, 48>(bufH, g_wh + WOFF3, sBias + 384, sWa, sWb, swa_bytes, swb_bytes, tid);
    stage_chunk(g_wh + WOFF4, swa_bytes, 96 * 8, tid);  CP_WAIT0(); __syncthreads();
    layer<96, 96, 48, 48>(bufH, g_wh + WOFF4, sBias + 480, sWa, sWb, swa_bytes, swb_bytes, tid);
    __syncthreads();

    // layer 5: 96 -> 1 (no activation); 4 threads per row; reconstruct hi+lo
    {
        const int r = tid >> 2, q = tid & 3;
        float acc = 0.f;
#pragma unroll
        for (int k = 0; k < 12; ++k) {
            int wcol = q * 12 + k;
            int pos = r * 48 + (wcol >> 4) * 16 + perm16(wcol & 15);
            float2 fh = __half22float2(*(const __half2*)(bufH + pos));
            float2 fl = __half22float2(*(const __half2*)(bufL + pos));
            acc = fmaf(fh.x + fl.x, sW5[2 * wcol], acc);
            acc = fmaf(fh.y + fl.y, sW5[2 * wcol + 1], acc);
        }
        acc += __shfl_xor_sync(0xffffffffu, acc, 1);
        acc += __shfl_xor_sync(0xffffffffu, acc, 2);
        if (q == 0) {
            float lg = acc + sB5;
            int j = j0 + r;
            g_logits[((size_t)b * NN + i) * NN + j] = lg;   // direct
            g_logits[((size_t)b * NN + j) * NN + i] = lg;   // mirror (d symmetric)
        }
    }
}

__global__ void __launch_bounds__(256)
softmax_kernel(float2* __restrict__ out)
{
    __shared__ float sred[8];
    __shared__ float sval;
    int row = blockIdx.x;
    int i   = row & (NN - 1);
    const float* L = g_logits + (size_t)row * NN;
    int tid  = threadIdx.x;
    int lane = tid & 31, warp = tid >> 5;

    float l0 = L[tid];
    float l1 = L[tid + 256];
    if (tid == i)       l0 -= 1e8f;
    if (tid + 256 == i) l1 -= 1e8f;

    float m = fmaxf(l0, l1);
#pragma unroll
    for (int o = 16; o > 0; o >>= 1) m = fmaxf(m, __shfl_xor_sync(0xffffffffu, m, o));
    if (lane == 0) sred[warp] = m;
    __syncthreads();
    if (tid == 0) {
        float v = sred[0];
        for (int w = 1; w < 8; ++w) v = fmaxf(v, sred[w]);
        sval = v;
    }
    __syncthreads();
    float M  = sval;
    float e0 = expf(l0 - M);
    float e1 = expf(l1 - M);
    float s  = e0 + e1;
#pragma unroll
    for (int o = 16; o > 0; o >>= 1) s += __shfl_xor_sync(0xffffffffu, s, o);
    __syncthreads();
    if (lane == 0) sred[warp] = s;
    __syncthreads();
    if (tid == 0) {
        float v = 0.f;
        for (int w = 0; w < 8; ++w) v += sred[w];
        sval = 1.0f / v;
    }
    __syncthreads();
    float inv = sval;

    float2* o2 = out + (size_t)row * NN;
    o2[tid]       = make_float2(tid == i ? 1.f : 0.f,       e0 * inv);
    o2[tid + 256] = make_float2(tid + 256 == i ? 1.f : 0.f, e1 * inv);
}

extern "C" void kernel_launch(void* const* d_in, const int* in_sizes, int n_in,
                              void* d_out, int out_size)
{
    const float* x  = (const float*)d_in[0];
    // d_in[1] = W_id (exact identity; regenerated analytically)
    const float* w1 = (const float*)d_in[2];
    const float* b1 = (const float*)d_in[3];
    const float* w2 = (const float*)d_in[4];
    const float* b2 = (const float*)d_in[5];
    const float* w3 = (const float*)d_in[6];
    const float* b3 = (const float*)d_in[7];
    const float* w4 = (const float*)d_in[8];
    const float* b4 = (const float*)d_in[9];
    const float* w5 = (const float*)d_in[10];
    const float* b5 = (const float*)d_in[11];
    float2* out = (float2*)d_out;

    // weight split (cheap, deterministic, graph-capturable)
    convert_weights<<<(192 * 64 + 255) / 256, 256>>>(w1, 192, 128, WOFF1);
    convert_weights<<<(192 * 96 + 255) / 256, 256>>>(w2, 192, 192, WOFF2);
    convert_weights<<<(96 * 96 + 255) / 256, 256>>>(w3, 96, 192, WOFF3);
    convert_weights<<<(96 * 48 + 255) / 256, 256>>>(w4, 96, 96, WOFF4);

    // dyn smem: 2 act planes (2*14336 w) + 2 weight buffers (2*192*32 w) = 163,840 B
    size_t smem_bytes = (2 * PL + 2 * 192 * 32) * sizeof(uint32_t);
    cudaFuncSetAttribute(mlp_kernel, cudaFuncAttributeMaxDynamicSharedMemorySize,
                         (int)smem_bytes);

    mlp_kernel<<<NB * 1280, 512, smem_bytes>>>(x, b1, b2, b3, b4, w5, b5);
    softmax_kernel<<<NB * NN, 256>>>(out);
}